// round 10
// baseline (speedup 1.0000x reference)
#include <cuda_runtime.h>
#include <cstdint>

// Problem constants
#define GM 9600          // B*Lq = 32*300
#define GK 256           // D_MODEL
#define NRAW 288         // 192 offset cols + 96 attn cols
#define BM 128
#define BN 96
#define BK 16

// Scratch for raw GEMM output (query @ [W_off | W_attn] + bias), ~11 MB.
__device__ float g_raw[GM * NRAW];

// ---- packed dual-fp32 FMA (sm_103a). One instr = 2 IEEE fp32 FMAs. ----
__device__ __forceinline__ unsigned long long fma_f32x2(
    unsigned long long a, unsigned long long b, unsigned long long c) {
    unsigned long long d;
    asm("fma.rn.f32x2 %0, %1, %2, %3;" : "=l"(d) : "l"(a), "l"(b), "l"(c));
    return d;
}
__device__ __forceinline__ unsigned long long pack2dup(float x) {
    unsigned long long r;
    asm("mov.b64 %0, {%1, %2};" : "=l"(r) : "f"(x), "f"(x));
    return r;
}
__device__ __forceinline__ void unpack2(unsigned long long p, float& lo, float& hi) {
    asm("mov.b64 {%0, %1}, %2;" : "=f"(lo), "=f"(hi) : "l"(p));
}

// ---------------------------------------------------------------------------
// Kernel 1: fused GEMM  raw[9600][288] = query @ [W_off(192) | W_attn(96)] + b
// Double-buffered SMEM fp32 GEMM, packed f32x2 FMAs, 8m x 6n microtile
// (LDS bytes/FMA = 1.17 vs 1.67 at 4x6 -> SMEM-bandwidth ceiling lowered 30%).
// grid = (75, 3): y=0,1 -> W_off halves, y=2 -> W_attn. 256 threads, 16x16.
// 225 blocks -> single wave at 2 blocks/SM.
// ---------------------------------------------------------------------------
__global__ __launch_bounds__(256) void dfine_gemm_kernel(
    const float* __restrict__ A,      // query (9600 x 256)
    const float* __restrict__ Woff,   // (256 x 192)
    const float* __restrict__ boff,   // (192)
    const float* __restrict__ Wattn,  // (256 x 96)
    const float* __restrict__ battn)  // (96)
{
    // As stride 132 floats: 16B-aligned rows (132*4 = 33*16) and only 2-way
    // STS conflict on the transposed store (4*132 = 528 ≡ 16 mod 32 words).
    __shared__ float As[2][BK][132];
    __shared__ float Bs[2][BK][BN];

    const int tid  = threadIdx.x;
    const int rowBase = blockIdx.x * BM;
    const int nblk = blockIdx.y;

    const float* Bsrc;
    const float* bias;
    int ldB, colBase, nGlobalBase;
    if (nblk < 2) { Bsrc = Woff;  bias = boff;  ldB = 192; colBase = nblk * 96; nGlobalBase = nblk * 96; }
    else          { Bsrc = Wattn; bias = battn; ldB = 96;  colBase = 0;         nGlobalBase = 192; }

    const int ty = tid >> 4;   // 0..15 (m) -> rows ty*8..ty*8+7
    const int tx = tid & 15;   // 0..15 (n) -> cols tx*6..tx*6+5

    // A-load mapping: 512 float4 per tile (128 rows x 4 k-quads), 2 per thread.
    const int rA0 = tid >> 2;          // 0..63
    const int rA1 = rA0 + 64;          // 64..127
    const int kqA = tid & 3;           // same k-quad for both

    unsigned long long acc2[8][3];     // [m][n-pair]
    #pragma unroll
    for (int i = 0; i < 8; i++)
        #pragma unroll
        for (int j = 0; j < 3; j++) acc2[i][j] = 0ull;

    float4 avr[2];
    float  bvr[6];

    // ---- prologue: tile 0 -> buf 0
    {
        avr[0] = *reinterpret_cast<const float4*>(A + (rowBase + rA0) * GK + kqA * 4);
        avr[1] = *reinterpret_cast<const float4*>(A + (rowBase + rA1) * GK + kqA * 4);
        #pragma unroll
        for (int i = 0; i < 6; i++) {
            int e = tid + i * 256;
            int k = e / 96;
            int n = e - k * 96;
            bvr[i] = __ldg(Bsrc + k * ldB + colBase + n);
        }
        #pragma unroll
        for (int j = 0; j < 4; j++) {
            As[0][kqA * 4 + j][rA0] = (&avr[0].x)[j];
            As[0][kqA * 4 + j][rA1] = (&avr[1].x)[j];
        }
        #pragma unroll
        for (int i = 0; i < 6; i++) {
            int e = tid + i * 256;
            int k = e / 96;
            int n = e - k * 96;
            Bs[0][k][n] = bvr[i];
        }
    }
    __syncthreads();

    const int NT = GK / BK;   // 16 tiles
    for (int t = 0; t < NT; t++) {
        const int cur = t & 1;
        if (t + 1 < NT) {
            const int k0 = (t + 1) * BK;
            avr[0] = *reinterpret_cast<const float4*>(A + (rowBase + rA0) * GK + k0 + kqA * 4);
            avr[1] = *reinterpret_cast<const float4*>(A + (rowBase + rA1) * GK + k0 + kqA * 4);
            #pragma unroll
            for (int i = 0; i < 6; i++) {
                int e = tid + i * 256;
                int k = e / 96;
                int n = e - k * 96;
                bvr[i] = __ldg(Bsrc + (k0 + k) * ldB + colBase + n);
            }
        }

        // compute: per k, 2x LDS.128 (A) + 3x LDS.64 (B) + 8 packs + 24 FFMA2
        #pragma unroll
        for (int k = 0; k < BK; k++) {
            float4 a0 = *reinterpret_cast<const float4*>(&As[cur][k][ty * 8]);
            float4 a1 = *reinterpret_cast<const float4*>(&As[cur][k][ty * 8 + 4]);
            unsigned long long a2[8];
            a2[0] = pack2dup(a0.x); a2[1] = pack2dup(a0.y);
            a2[2] = pack2dup(a0.z); a2[3] = pack2dup(a0.w);
            a2[4] = pack2dup(a1.x); a2[5] = pack2dup(a1.y);
            a2[6] = pack2dup(a1.z); a2[7] = pack2dup(a1.w);
            unsigned long long b2[3];
            b2[0] = *reinterpret_cast<const unsigned long long*>(&Bs[cur][k][tx * 6 + 0]);
            b2[1] = *reinterpret_cast<const unsigned long long*>(&Bs[cur][k][tx * 6 + 2]);
            b2[2] = *reinterpret_cast<const unsigned long long*>(&Bs[cur][k][tx * 6 + 4]);
            #pragma unroll
            for (int i = 0; i < 8; i++)
                #pragma unroll
                for (int j = 0; j < 3; j++)
                    acc2[i][j] = fma_f32x2(a2[i], b2[j], acc2[i][j]);
        }

        if (t + 1 < NT) {
            const int nxt = 1 - cur;
            #pragma unroll
            for (int j = 0; j < 4; j++) {
                As[nxt][kqA * 4 + j][rA0] = (&avr[0].x)[j];
                As[nxt][kqA * 4 + j][rA1] = (&avr[1].x)[j];
            }
            #pragma unroll
            for (int i = 0; i < 6; i++) {
                int e = tid + i * 256;
                int k = e / 96;
                int n = e - k * 96;
                Bs[nxt][k][n] = bvr[i];
            }
        }
        __syncthreads();
    }

    // ---- epilogue: unpack, add bias, float2 stores to g_raw
    #pragma unroll
    for (int i = 0; i < 8; i++) {
        int r = rowBase + ty * 8 + i;
        #pragma unroll
        for (int j = 0; j < 3; j++) {
            float lo, hi;
            unpack2(acc2[i][j], lo, hi);
            int n = tx * 6 + 2 * j;
            float2 v = make_float2(lo + __ldg(bias + colBase + n + 0),
                                   hi + __ldg(bias + colBase + n + 1));
            *reinterpret_cast<float2*>(&g_raw[r * NRAW + nGlobalBase + n]) = v;
        }
    }
}

// ---------------------------------------------------------------------------
// Kernel 2: fused softmax + location transform + bilinear gather + weighted sum
// (R8 version — predicated corner loads; measured 43.7 us.)
// Block = 256 threads = 4 queries x 64 threads; thread = 4 channels (float4).
// ---------------------------------------------------------------------------
__global__ __launch_bounds__(256) void dfine_sample_kernel(
    const float* __restrict__ refp,   // (32,300,1,4)
    const float* __restrict__ value,  // input_flatten (32, 8400, 256)
    float* __restrict__ out)          // (32,300,256)
{
    __shared__ int   sOffs[4][96][4];  // absolute spatial index (0..8399) or -1
    __shared__ float sWts[4][96][4];   // bilinear weights * softmax weight
    __shared__ float sLog[4][96];      // attn logits -> probabilities

    const int tid  = threadIdx.x;
    const int row0 = blockIdx.x * 4;   // 300 % 4 == 0 -> never straddles a batch

    // ---- Phase A: per-(query,head,point) address/weight precompute
    #pragma unroll
    for (int e = tid; e < 384; e += 256) {
        int qi = e / 96, j = e % 96;       // j = h*12 + pt
        int row = row0 + qi;
        const float* raw = g_raw + (size_t)row * NRAW;
        float rx = __ldg(refp + row * 4 + 0);
        float ry = __ldg(refp + row * 4 + 1);
        float rw = __ldg(refp + row * 4 + 2);
        float rh = __ldg(refp + row * 4 + 3);
        float ox = raw[2 * j + 0];
        float oy = raw[2 * j + 1];
        sLog[qi][j] = raw[192 + j];

        int pt  = j % 12;
        int lvl = pt >> 2;
        int   W    = (lvl == 0) ? 80 : (lvl == 1) ? 40 : 20;  // H == W
        int   loff = (lvl == 0) ? 0  : (lvl == 1) ? 6400 : 8000;
        float Wf   = (float)W;
        // pscale=1/4, OFFSET_SCALE=0.5 -> 0.125; pixel = loc*W - 0.5
        float ix = (rx + ox * 0.125f * rw) * Wf - 0.5f;
        float iy = (ry + oy * 0.125f * rh) * Wf - 0.5f;
        float fx0 = floorf(ix), fy0 = floorf(iy);
        float fx = ix - fx0, fy = iy - fy0;
        int x0 = (int)fx0, y0 = (int)fy0;
        int x1 = x0 + 1,   y1 = y0 + 1;
        bool vx0 = (unsigned)x0 < (unsigned)W;
        bool vx1 = (unsigned)x1 < (unsigned)W;
        bool vy0 = (unsigned)y0 < (unsigned)W;
        bool vy1 = (unsigned)y1 < (unsigned)W;
        sOffs[qi][j][0] = (vx0 && vy0) ? (loff + y0 * W + x0) : -1;
        sOffs[qi][j][1] = (vx1 && vy0) ? (loff + y0 * W + x1) : -1;
        sOffs[qi][j][2] = (vx0 && vy1) ? (loff + y1 * W + x0) : -1;
        sOffs[qi][j][3] = (vx1 && vy1) ? (loff + y1 * W + x1) : -1;
        float gx = 1.0f - fx, gy = 1.0f - fy;
        sWts[qi][j][0] = gx * gy;
        sWts[qi][j][1] = fx * gy;
        sWts[qi][j][2] = gx * fy;
        sWts[qi][j][3] = fx * fy;
    }
    __syncthreads();

    // ---- Phase B: per-(query,head) softmax over 12 points (in place)
    if (tid < 32) {
        int qi = tid >> 3, h = tid & 7;
        float* L = &sLog[qi][h * 12];
        float m = -1e30f;
        #pragma unroll
        for (int p = 0; p < 12; p++) m = fmaxf(m, L[p]);
        float s = 0.0f;
        #pragma unroll
        for (int p = 0; p < 12; p++) { float ev = expf(L[p] - m); L[p] = ev; s += ev; }
        float inv = 1.0f / s;
        #pragma unroll
        for (int p = 0; p < 12; p++) L[p] *= inv;
    }
    __syncthreads();

    // ---- Phase C: fold softmax weight into bilinear weights
    #pragma unroll
    for (int e = tid; e < 384; e += 256) {
        int qi = e / 96, j = e % 96;
        float w = sLog[qi][j];
        sWts[qi][j][0] *= w;
        sWts[qi][j][1] *= w;
        sWts[qi][j][2] *= w;
        sWts[qi][j][3] *= w;
    }
    __syncthreads();

    // ---- Phase D: gather + accumulate. 64 threads/query, float4 channels.
    const int qi   = tid >> 6;         // query within block
    const int lane = tid & 63;         // channel-quad index 0..63
    const int h    = lane >> 3;        // head (8 channel-quads per head)
    const int row  = row0 + qi;
    const int b    = row / 300;

    const float4* __restrict__ vb =
        (const float4*)value + (size_t)b * 8400 * 64 + h * 8 + (lane & 7);

    float4 acc = make_float4(0.0f, 0.0f, 0.0f, 0.0f);
    #pragma unroll 4
    for (int pt = 0; pt < 12; pt++) {
        int j = h * 12 + pt;
        int4   o = *reinterpret_cast<const int4*>(sOffs[qi][j]);
        float4 w = *reinterpret_cast<const float4*>(sWts[qi][j]);
        if (o.x >= 0) {
            float4 v = __ldg(vb + (size_t)o.x * 64);
            acc.x += w.x * v.x; acc.y += w.x * v.y; acc.z += w.x * v.z; acc.w += w.x * v.w;
        }
        if (o.y >= 0) {
            float4 v = __ldg(vb + (size_t)o.y * 64);
            acc.x += w.y * v.x; acc.y += w.y * v.y; acc.z += w.y * v.z; acc.w += w.y * v.w;
        }
        if (o.z >= 0) {
            float4 v = __ldg(vb + (size_t)o.z * 64);
            acc.x += w.z * v.x; acc.y += w.z * v.y; acc.z += w.z * v.z; acc.w += w.z * v.w;
        }
        if (o.w >= 0) {
            float4 v = __ldg(vb + (size_t)o.w * 64);
            acc.x += w.w * v.x; acc.y += w.w * v.y; acc.z += w.w * v.z; acc.w += w.w * v.w;
        }
    }

    reinterpret_cast<float4*>(out)[(size_t)row * 64 + lane] = acc;
}

// ---------------------------------------------------------------------------
// Launch: inputs in metadata order:
//   0 query (32,300,256) f32        1 reference_points (32,300,1,4) f32
//   2 input_flatten (32,8400,256)   3 W_off (256,192)   4 b_off (192)
//   5 W_attn (256,96)               6 b_attn (96)
// Output: (32,300,256) f32
// ---------------------------------------------------------------------------
extern "C" void kernel_launch(void* const* d_in, const int* in_sizes, int n_in,
                              void* d_out, int out_size) {
    const float* query = (const float*)d_in[0];
    const float* refp  = (const float*)d_in[1];
    const float* value = (const float*)d_in[2];
    const float* Woff  = (const float*)d_in[3];
    const float* boff  = (const float*)d_in[4];
    const float* Wattn = (const float*)d_in[5];
    const float* battn = (const float*)d_in[6];
    float* out = (float*)d_out;

    dim3 ggrid(GM / BM, 3);  // 75 x 3
    dfine_gemm_kernel<<<ggrid, 256>>>(query, Woff, boff, Wattn, battn);
    dfine_sample_kernel<<<GM / 4, 256>>>(refp, value, out);
}